// round 4
// baseline (speedup 1.0000x reference)
#include <cuda_runtime.h>

// Problem constants: x,y are (1,1,192,192,192) f32.
#define Wd 192
#define Hd 192
#define Dd 192
#define NVOX (Wd*Hd*Dd)          // 7,077,888
#define N4   (NVOX/4)            // 1,769,472

#define RED_BLOCKS 1184
#define RED_THREADS 256

// Scratch (no allocation allowed in kernel_launch).
__device__ float g_part[RED_BLOCKS][8];
__device__ float g_t[3];

static __device__ __forceinline__ float warp_sum(float v) {
    #pragma unroll
    for (int o = 16; o > 0; o >>= 1) v += __shfl_down_sync(0xffffffffu, v, o);
    return v;
}

// ---------------------------------------------------------------------------
// Kernel 1: per-block partial sums of 8 quantities:
//  [0]=sum x, [1]=sum x*gx, [2]=sum x*gy, [3]=sum x*gz, [4..7] same for y.
// gx depends only on w, gy on h, gz on d (linspace(-1,1,.)).
// ---------------------------------------------------------------------------
__global__ __launch_bounds__(RED_THREADS) void reduce_kernel(
    const float* __restrict__ x, const float* __restrict__ y)
{
    const float step = 2.0f / (float)(Wd - 1);
    float a[8];
    #pragma unroll
    for (int i = 0; i < 8; i++) a[i] = 0.0f;

    const float4* __restrict__ x4 = (const float4*)x;
    const float4* __restrict__ y4 = (const float4*)y;

    for (int j = blockIdx.x * blockDim.x + threadIdx.x; j < N4;
         j += gridDim.x * blockDim.x)
    {
        int e  = j * 4;                 // element index of .x
        int w  = e % Wd;                // row-aligned: all 4 in one row (192%4==0)
        int hd = e / Wd;
        int h  = hd % Hd;
        int d  = hd / Hd;

        float gx0 = fmaf((float)(w+0), step, -1.0f);
        float gx1 = fmaf((float)(w+1), step, -1.0f);
        float gx2 = fmaf((float)(w+2), step, -1.0f);
        float gx3 = fmaf((float)(w+3), step, -1.0f);
        float gy  = fmaf((float)h, step, -1.0f);
        float gz  = fmaf((float)d, step, -1.0f);

        float4 vx = __ldg(&x4[j]);
        float sx = (vx.x + vx.y) + (vx.z + vx.w);
        a[0] += sx;
        a[1] += vx.x*gx0 + vx.y*gx1 + vx.z*gx2 + vx.w*gx3;
        a[2] += sx * gy;
        a[3] += sx * gz;

        float4 vy = __ldg(&y4[j]);
        float sy = (vy.x + vy.y) + (vy.z + vy.w);
        a[4] += sy;
        a[5] += vy.x*gx0 + vy.y*gx1 + vy.z*gx2 + vy.w*gx3;
        a[6] += sy * gy;
        a[7] += sy * gz;
    }

    __shared__ float sh[8][8];   // [warp][quantity]
    int lane = threadIdx.x & 31;
    int warp = threadIdx.x >> 5;
    #pragma unroll
    for (int q = 0; q < 8; q++) {
        float v = warp_sum(a[q]);
        if (lane == 0) sh[warp][q] = v;
    }
    __syncthreads();
    if (warp == 0) {
        #pragma unroll
        for (int q = 0; q < 8; q++) {
            float v = (lane < 8) ? sh[lane][q] : 0.0f;
            v = warp_sum(v);
            if (lane == 0) g_part[blockIdx.x][q] = v;
        }
    }
}

// ---------------------------------------------------------------------------
// Kernel 2: final reduce of partials + compute t = cm_x - cm_y (deterministic).
// One block of 256 threads: warp q reduces quantity q.
// ---------------------------------------------------------------------------
__global__ __launch_bounds__(256) void finalize_kernel()
{
    __shared__ float s[8];
    int lane = threadIdx.x & 31;
    int q    = threadIdx.x >> 5;   // 0..7
    float acc = 0.0f;
    for (int i = lane; i < RED_BLOCKS; i += 32) acc += g_part[i][q];
    acc = warp_sum(acc);
    if (lane == 0) s[q] = acc;
    __syncthreads();
    if (threadIdx.x == 0) {
        float inv_sx = 1.0f / s[0];
        float inv_sy = 1.0f / s[4];
        g_t[0] = s[1] * inv_sx - s[5] * inv_sy;
        g_t[1] = s[2] * inv_sx - s[6] * inv_sy;
        g_t[2] = s[3] * inv_sx - s[7] * inv_sy;
    }
}

// ---------------------------------------------------------------------------
// Kernel 3: write grid = base + t and transformed = trilinear(x, grid).
// 4 voxels (along w) per thread; float4 stores for both outputs.
// ---------------------------------------------------------------------------
__global__ __launch_bounds__(256) void sample_kernel(
    const float* __restrict__ vol,
    float* __restrict__ out_t,      // NVOX floats
    float* __restrict__ out_g)      // NVOX*3 floats
{
    int j = blockIdx.x * blockDim.x + threadIdx.x;
    if (j >= N4) return;

    const float step = 2.0f / (float)(Wd - 1);
    const float tx = g_t[0], ty = g_t[1], tz = g_t[2];

    int e  = j * 4;
    int w0 = e % Wd;
    int hd = e / Wd;
    int h  = hd % Hd;
    int d  = hd / Hd;

    float gy = fmaf((float)h, step, -1.0f);
    float gz = fmaf((float)d, step, -1.0f);
    float goy = gy + ty;
    float goz = gz + tz;

    // y/z sample coords are shared by all 4 voxels in this thread.
    float iy = (goy + 1.0f) * 0.5f * (float)(Hd - 1);
    float iz = (goz + 1.0f) * 0.5f * (float)(Dd - 1);
    float iy0f = floorf(iy), iz0f = floorf(iz);
    float wy = iy - iy0f,    wz = iz - iz0f;
    int iy0 = (int)iy0f, iz0 = (int)iz0f;
    int iy1 = iy0 + 1,   iz1 = iz0 + 1;

    float vy0 = (iy0 >= 0 && iy0 < Hd) ? 1.0f : 0.0f;
    float vy1 = (iy1 >= 0 && iy1 < Hd) ? 1.0f : 0.0f;
    float vz0 = (iz0 >= 0 && iz0 < Dd) ? 1.0f : 0.0f;
    float vz1 = (iz1 >= 0 && iz1 < Dd) ? 1.0f : 0.0f;
    int cy0 = min(max(iy0, 0), Hd - 1);
    int cy1 = min(max(iy1, 0), Hd - 1);
    int cz0 = min(max(iz0, 0), Dd - 1);
    int cz1 = min(max(iz1, 0), Dd - 1);

    // Row base offsets for the 4 (z,y) corner rows.
    long b00 = (long)cz0 * (Hd * Wd) + (long)cy0 * Wd;
    long b01 = (long)cz0 * (Hd * Wd) + (long)cy1 * Wd;
    long b10 = (long)cz1 * (Hd * Wd) + (long)cy0 * Wd;
    long b11 = (long)cz1 * (Hd * Wd) + (long)cy1 * Wd;

    // Combined (z,y) weights incl. validity.
    float q00 = (1.0f - wz) * (1.0f - wy) * vz0 * vy0;
    float q01 = (1.0f - wz) * wy          * vz0 * vy1;
    float q10 = wz          * (1.0f - wy) * vz1 * vy0;
    float q11 = wz          * wy          * vz1 * vy1;

    float tr[4];
    float gg[12];

    #pragma unroll
    for (int k = 0; k < 4; k++) {
        int w = w0 + k;
        float gx  = fmaf((float)w, step, -1.0f);
        float gox = gx + tx;
        gg[3*k + 0] = gox;
        gg[3*k + 1] = goy;
        gg[3*k + 2] = goz;

        float ix = (gox + 1.0f) * 0.5f * (float)(Wd - 1);
        float ix0f = floorf(ix);
        float wx = ix - ix0f;
        int ix0 = (int)ix0f;
        int ix1 = ix0 + 1;
        float vx0 = (ix0 >= 0 && ix0 < Wd) ? 1.0f : 0.0f;
        float vx1 = (ix1 >= 0 && ix1 < Wd) ? 1.0f : 0.0f;
        int cx0 = min(max(ix0, 0), Wd - 1);
        int cx1 = min(max(ix1, 0), Wd - 1);
        float wxa = (1.0f - wx) * vx0;
        float wxb = wx * vx1;

        float v00 = __ldg(&vol[b00 + cx0]) * wxa + __ldg(&vol[b00 + cx1]) * wxb;
        float v01 = __ldg(&vol[b01 + cx0]) * wxa + __ldg(&vol[b01 + cx1]) * wxb;
        float v10 = __ldg(&vol[b10 + cx0]) * wxa + __ldg(&vol[b10 + cx1]) * wxb;
        float v11 = __ldg(&vol[b11 + cx0]) * wxa + __ldg(&vol[b11 + cx1]) * wxb;

        tr[k] = q00 * v00 + q01 * v01 + q10 * v10 + q11 * v11;
    }

    // Vector stores: transformed (1×float4) and grid (3×float4, 12 floats/thread).
    ((float4*)out_t)[j] = make_float4(tr[0], tr[1], tr[2], tr[3]);
    float4* g4 = (float4*)(out_g + (long)e * 3);   // e*3 = j*12, 16B-aligned
    g4[0] = make_float4(gg[0], gg[1], gg[2],  gg[3]);
    g4[1] = make_float4(gg[4], gg[5], gg[6],  gg[7]);
    g4[2] = make_float4(gg[8], gg[9], gg[10], gg[11]);
}

// ---------------------------------------------------------------------------
extern "C" void kernel_launch(void* const* d_in, const int* in_sizes, int n_in,
                              void* d_out, int out_size)
{
    const float* x = (const float*)d_in[0];
    const float* y = (const float*)d_in[1];
    float* out_transformed = (float*)d_out;            // NVOX floats
    float* out_grid        = (float*)d_out + NVOX;     // NVOX*3 floats

    reduce_kernel<<<RED_BLOCKS, RED_THREADS>>>(x, y);
    finalize_kernel<<<1, 256>>>();
    sample_kernel<<<(N4 + 255) / 256, 256>>>(x, out_transformed, out_grid);
}

// round 7
// speedup vs baseline: 1.2358x; 1.2358x over previous
#include <cuda_runtime.h>

// Problem constants: x,y are (1,1,192,192,192) f32.
#define Wd 192
#define Hd 192
#define Dd 192
#define NVOX (Wd*Hd*Dd)          // 7,077,888
#define N4   (NVOX/4)            // 1,769,472

#define RED_BLOCKS 1152
#define RED_THREADS 256
#define RED_ITERS 6
#define RED_STRIDE (RED_BLOCKS*RED_THREADS)   // 294,912 ; *6 == N4 exactly

#define SAMP_THREADS 256
#define SAMP_BLOCKS (N4 / SAMP_THREADS)       // 6912 exactly

// Scratch (no allocation allowed in kernel_launch).
__device__ float g_part[RED_BLOCKS][8];
__device__ float g_t[3];
__device__ unsigned g_count;   // zero at load; reset by last block each run

static __device__ __forceinline__ float warp_sum(float v) {
    #pragma unroll
    for (int o = 16; o > 0; o >>= 1) v += __shfl_down_sync(0xffffffffu, v, o);
    return v;
}

// ---------------------------------------------------------------------------
// Kernel 1: per-block partial sums of 8 quantities + fused final reduce in the
// last finished block. Quantities:
//  [0]=sum x, [1]=sum x*gx, [2]=sum x*gy, [3]=sum x*gz, [4..7] same for y.
// Exact tiling: RED_BLOCKS*RED_THREADS*RED_ITERS == N4 (no bounds checks).
// ---------------------------------------------------------------------------
__global__ __launch_bounds__(RED_THREADS) void reduce_kernel(
    const float* __restrict__ x, const float* __restrict__ y)
{
    const float step = 2.0f / (float)(Wd - 1);
    float a[8];
    #pragma unroll
    for (int i = 0; i < 8; i++) a[i] = 0.0f;

    const float4* __restrict__ x4 = (const float4*)x;
    const float4* __restrict__ y4 = (const float4*)y;

    int j0 = blockIdx.x * RED_THREADS + threadIdx.x;

    // Front-batched loads for MLP. y is never reused -> streaming hint.
    float4 vx[RED_ITERS], vy[RED_ITERS];
    #pragma unroll
    for (int i = 0; i < RED_ITERS; i++) {
        vx[i] = __ldg(&x4[j0 + i * RED_STRIDE]);
        vy[i] = __ldcs(&y4[j0 + i * RED_STRIDE]);
    }

    #pragma unroll
    for (int i = 0; i < RED_ITERS; i++) {
        int j  = j0 + i * RED_STRIDE;
        int e  = j * 4;                 // element index of .x
        int w  = e % Wd;                // row-aligned: all 4 in one row
        int hd = e / Wd;
        int h  = hd % Hd;
        int d  = hd / Hd;

        float gx0 = fmaf((float)(w+0), step, -1.0f);
        float gx1 = fmaf((float)(w+1), step, -1.0f);
        float gx2 = fmaf((float)(w+2), step, -1.0f);
        float gx3 = fmaf((float)(w+3), step, -1.0f);
        float gy  = fmaf((float)h, step, -1.0f);
        float gz  = fmaf((float)d, step, -1.0f);

        float sx = (vx[i].x + vx[i].y) + (vx[i].z + vx[i].w);
        a[0] += sx;
        a[1] += vx[i].x*gx0 + vx[i].y*gx1 + vx[i].z*gx2 + vx[i].w*gx3;
        a[2] += sx * gy;
        a[3] += sx * gz;

        float sy = (vy[i].x + vy[i].y) + (vy[i].z + vy[i].w);
        a[4] += sy;
        a[5] += vy[i].x*gx0 + vy[i].y*gx1 + vy[i].z*gx2 + vy[i].w*gx3;
        a[6] += sy * gy;
        a[7] += sy * gz;
    }

    __shared__ float sh[8][8];   // [warp][quantity]
    int lane = threadIdx.x & 31;
    int warp = threadIdx.x >> 5;
    #pragma unroll
    for (int q = 0; q < 8; q++) {
        float v = warp_sum(a[q]);
        if (lane == 0) sh[warp][q] = v;
    }
    __syncthreads();
    if (warp == 0) {
        #pragma unroll
        for (int q = 0; q < 8; q++) {
            float v = (lane < 8) ? sh[lane][q] : 0.0f;
            v = warp_sum(v);
            if (lane == 0) g_part[blockIdx.x][q] = v;
        }
    }

    // ---- fused finalize: last finished block reduces the partials ----
    __shared__ bool is_last;
    __threadfence();
    if (threadIdx.x == 0)
        is_last = (atomicAdd(&g_count, 1u) == (unsigned)(RED_BLOCKS - 1));
    __syncthreads();
    if (!is_last) return;
    __threadfence();

    {
        __shared__ float s[8];
        int q = threadIdx.x >> 5;       // 8 warps, one quantity each
        float acc = 0.0f;
        for (int i = lane; i < RED_BLOCKS; i += 32) acc += g_part[i][q];
        acc = warp_sum(acc);
        if (lane == 0) s[q] = acc;
        __syncthreads();
        if (threadIdx.x == 0) {
            float inv_sx = 1.0f / s[0];
            float inv_sy = 1.0f / s[4];
            g_t[0] = s[1] * inv_sx - s[5] * inv_sy;
            g_t[1] = s[2] * inv_sx - s[6] * inv_sy;
            g_t[2] = s[3] * inv_sx - s[7] * inv_sy;
            g_count = 0;                // reset for next graph replay
        }
    }
}

// ---------------------------------------------------------------------------
// Kernel 2: write grid = base + t and transformed = trilinear(x, grid).
// 4 voxels (along w) per thread. Since t is a constant shift, ix0 == w + c with
// uniform c in {0,-1}: each of the 4 corner rows needs only x-elements
// [w0-1 .. w0+4], fetched as one aligned float4 + one scalar (8 LDGs/thread vs
// 32 scalar LDGs). Fast paths are validated against the exactly-computed
// per-voxel indices so results are bitwise identical to the scalar path.
// NOTE: all fast-path addresses are rb[r] + <x-index>; rb[r] carries the z,y
// offset (this was the round-5 bug: it used the full linear index e).
// ---------------------------------------------------------------------------
__global__ __launch_bounds__(SAMP_THREADS) void sample_kernel(
    const float* __restrict__ vol,
    float* __restrict__ out_t,      // NVOX floats
    float* __restrict__ out_g)      // NVOX*3 floats
{
    int j = blockIdx.x * SAMP_THREADS + threadIdx.x;   // exact tiling, no guard

    const float step = 2.0f / (float)(Wd - 1);
    const float tx = g_t[0], ty = g_t[1], tz = g_t[2];

    int e  = j * 4;
    int w0 = e % Wd;
    int hd = e / Wd;
    int h  = hd % Hd;
    int d  = hd / Hd;

    float gy = fmaf((float)h, step, -1.0f);
    float gz = fmaf((float)d, step, -1.0f);
    float goy = gy + ty;
    float goz = gz + tz;

    // y/z sample coords are shared by all 4 voxels in this thread.
    float iy = (goy + 1.0f) * 0.5f * (float)(Hd - 1);
    float iz = (goz + 1.0f) * 0.5f * (float)(Dd - 1);
    float iy0f = floorf(iy), iz0f = floorf(iz);
    float wy = iy - iy0f,    wz = iz - iz0f;
    int iy0 = (int)iy0f, iz0 = (int)iz0f;
    int iy1 = iy0 + 1,   iz1 = iz0 + 1;

    float vy0 = (iy0 >= 0 && iy0 < Hd) ? 1.0f : 0.0f;
    float vy1 = (iy1 >= 0 && iy1 < Hd) ? 1.0f : 0.0f;
    float vz0 = (iz0 >= 0 && iz0 < Dd) ? 1.0f : 0.0f;
    float vz1 = (iz1 >= 0 && iz1 < Dd) ? 1.0f : 0.0f;
    int cy0 = min(max(iy0, 0), Hd - 1);
    int cy1 = min(max(iy1, 0), Hd - 1);
    int cz0 = min(max(iz0, 0), Dd - 1);
    int cz1 = min(max(iz1, 0), Dd - 1);

    long rb[4];
    rb[0] = (long)cz0 * (Hd * Wd) + (long)cy0 * Wd;   // b00
    rb[1] = (long)cz0 * (Hd * Wd) + (long)cy1 * Wd;   // b01
    rb[2] = (long)cz1 * (Hd * Wd) + (long)cy0 * Wd;   // b10
    rb[3] = (long)cz1 * (Hd * Wd) + (long)cy1 * Wd;   // b11

    float qq[4];
    qq[0] = (1.0f - wz) * (1.0f - wy) * vz0 * vy0;
    qq[1] = (1.0f - wz) * wy          * vz0 * vy1;
    qq[2] = wz          * (1.0f - wy) * vz1 * vy0;
    qq[3] = wz          * wy          * vz1 * vy1;

    // Per-voxel x coordinates (exact, same arithmetic as the reference path).
    float wxa[4], wxb[4];
    int   cx0a[4], cx1a[4];
    float gg[12];
    #pragma unroll
    for (int k = 0; k < 4; k++) {
        int w = w0 + k;
        float gx  = fmaf((float)w, step, -1.0f);
        float gox = gx + tx;
        gg[3*k + 0] = gox;
        gg[3*k + 1] = goy;
        gg[3*k + 2] = goz;

        float ix = (gox + 1.0f) * 0.5f * (float)(Wd - 1);
        float ix0f = floorf(ix);
        float wx = ix - ix0f;
        int ix0 = (int)ix0f;
        int ix1 = ix0 + 1;
        float vx0 = (ix0 >= 0 && ix0 < Wd) ? 1.0f : 0.0f;
        float vx1 = (ix1 >= 0 && ix1 < Wd) ? 1.0f : 0.0f;
        cx0a[k] = min(max(ix0, 0), Wd - 1);
        cx1a[k] = min(max(ix1, 0), Wd - 1);
        wxa[k] = (1.0f - wx) * vx0;
        wxb[k] = wx * vx1;
    }

    int ce3 = min(w0 + 4, Wd - 1);   // expected clamped cx1 for k=3, shift 0
    int cm0 = max(w0 - 1, 0);        // expected clamped cx0 for k=0, shift -1

    bool f0 = (cx0a[0]==w0)   & (cx0a[1]==w0+1) & (cx0a[2]==w0+2) & (cx0a[3]==w0+3)
            & (cx1a[0]==w0+1) & (cx1a[1]==w0+2) & (cx1a[2]==w0+3) & (cx1a[3]==ce3);
    bool fm = (cx0a[0]==cm0)  & (cx0a[1]==w0)   & (cx0a[2]==w0+1) & (cx0a[3]==w0+2)
            & (cx1a[0]==w0)   & (cx1a[1]==w0+1) & (cx1a[2]==w0+2) & (cx1a[3]==w0+3);

    float tr[4] = {0.0f, 0.0f, 0.0f, 0.0f};

    if (f0) {
        // window: A = vol[rb + w0 .. w0+3], R = vol[rb + ce3]
        float4 A[4]; float Rs[4];
        #pragma unroll
        for (int r = 0; r < 4; r++) {
            A[r]  = __ldg((const float4*)(vol + rb[r] + w0));
            Rs[r] = __ldg(vol + rb[r] + ce3);
        }
        #pragma unroll
        for (int r = 0; r < 4; r++) {
            tr[0] += qq[r] * (A[r].x * wxa[0] + A[r].y * wxb[0]);
            tr[1] += qq[r] * (A[r].y * wxa[1] + A[r].z * wxb[1]);
            tr[2] += qq[r] * (A[r].z * wxa[2] + A[r].w * wxb[2]);
            tr[3] += qq[r] * (A[r].w * wxa[3] + Rs[r]  * wxb[3]);
        }
    } else if (fm) {
        // window: L = vol[rb + cm0], A = vol[rb + w0 .. w0+3]
        float4 A[4]; float Ls[4];
        #pragma unroll
        for (int r = 0; r < 4; r++) {
            A[r]  = __ldg((const float4*)(vol + rb[r] + w0));
            Ls[r] = __ldg(vol + rb[r] + cm0);
        }
        #pragma unroll
        for (int r = 0; r < 4; r++) {
            tr[0] += qq[r] * (Ls[r]  * wxa[0] + A[r].x * wxb[0]);
            tr[1] += qq[r] * (A[r].x * wxa[1] + A[r].y * wxb[1]);
            tr[2] += qq[r] * (A[r].y * wxa[2] + A[r].z * wxb[2]);
            tr[3] += qq[r] * (A[r].z * wxa[3] + A[r].w * wxb[3]);
        }
    } else {
        // General fallback: exact scalar gathers (rare: |shift| >= 1 or
        // inconsistent rounding flips).
        #pragma unroll
        for (int k = 0; k < 4; k++) {
            int cx0 = cx0a[k], cx1 = cx1a[k];
            #pragma unroll
            for (int r = 0; r < 4; r++) {
                float v = __ldg(&vol[rb[r] + cx0]) * wxa[k]
                        + __ldg(&vol[rb[r] + cx1]) * wxb[k];
                tr[k] += qq[r] * v;
            }
        }
    }

    // Streaming vector stores (output never re-read; keep x resident in L2).
    __stcs(((float4*)out_t) + j, make_float4(tr[0], tr[1], tr[2], tr[3]));
    float4* g4 = (float4*)(out_g + (long)e * 3);   // e*3 = j*12, 16B-aligned
    __stcs(g4 + 0, make_float4(gg[0], gg[1], gg[2],  gg[3]));
    __stcs(g4 + 1, make_float4(gg[4], gg[5], gg[6],  gg[7]));
    __stcs(g4 + 2, make_float4(gg[8], gg[9], gg[10], gg[11]));
}

// ---------------------------------------------------------------------------
extern "C" void kernel_launch(void* const* d_in, const int* in_sizes, int n_in,
                              void* d_out, int out_size)
{
    const float* x = (const float*)d_in[0];
    const float* y = (const float*)d_in[1];
    float* out_transformed = (float*)d_out;            // NVOX floats
    float* out_grid        = (float*)d_out + NVOX;     // NVOX*3 floats

    reduce_kernel<<<RED_BLOCKS, RED_THREADS>>>(x, y);
    sample_kernel<<<SAMP_BLOCKS, SAMP_THREADS>>>(x, out_transformed, out_grid);
}